// round 3
// baseline (speedup 1.0000x reference)
#include <cuda_runtime.h>
#include <math.h>
#include <stdint.h>

// Problem constants (fixed shapes)
#define NB   32
#define SEQ  512
#define EMB  128
#define BSE  (NB*SEQ*EMB)

// ---------------------------------------------------------------------------
// Scratch (static device arrays; no allocations allowed)
// ---------------------------------------------------------------------------
__device__ float g_Q [BSE];
__device__ float g_K [BSE];
__device__ float g_V [BSE];
__device__ float g_Ke[BSE];
__device__ float g_Ve[BSE];
__device__ float g_O1[BSE];
__device__ float g_O2[BSE];
__device__ float g_MH[BSE];

enum { JOB_Q = 0, JOB_K, JOB_V, JOB_KE, JOB_VE, JOB_MH };

// dynamic smem sizes
constexpr int GEMM_SMEM  = 64*132*4 + 128*32*16;              // 99328 B
constexpr int ATTN_SMEM  = (64*128 + 64*128 + 64*64) * 4;     // 81920 B
constexpr int FINAL_SMEM = (32*132 + 64*132 + 32*516) * 4;    // 116736 B

// ---------------------------------------------------------------------------
// Multi-pair GEMM: Y[16384,128] = sum_p Xp[16384,128] @ Wp[128,128] (+bias0+bias1)
// Block: 64 rows x 128 cols, 256 threads, each thread 2 rows x 16 cols.
// ---------------------------------------------------------------------------
__global__ __launch_bounds__(256)
void gemm128(int job,
             const float* __restrict__ x0, const float* __restrict__ x1,
             const float* __restrict__ x2, const float* __restrict__ x3,
             const float* __restrict__ w0, const float* __restrict__ w1,
             const float* __restrict__ w2, const float* __restrict__ w3,
             const float* __restrict__ bias0, const float* __restrict__ bias1)
{
    extern __shared__ float sm[];
    float*  sX = sm;                         // [64][132]
    float4* sW = (float4*)(sm + 64*132);     // [128][32] float4

    const float* Xs[4] = {x0, x1, x2, x3};
    const float* Ws[4] = {w0, w1, w2, w3};
    float* Y; int npair;
    switch (job) {
        case JOB_Q:  Y = g_Q;  npair = 4; break;
        case JOB_K:  Y = g_K;  npair = 1; break;
        case JOB_V:  Y = g_V;  npair = 1; break;
        case JOB_KE: Y = g_Ke; npair = 1; break;
        case JOB_VE: Y = g_Ve; npair = 1; break;
        default:     Y = g_MH; npair = 2; Xs[0] = g_O1; Xs[1] = g_O2; break;
    }

    const int tid  = threadIdx.x;
    const int row0 = blockIdx.x * 64;
    const int r    = tid >> 3;   // 0..31
    const int cg   = tid & 7;    // cols 4*(cg+8j)+0..3

    float4 acc[2][4];
    #pragma unroll
    for (int a = 0; a < 2; ++a)
        #pragma unroll
        for (int j = 0; j < 4; ++j) acc[a][j] = make_float4(0.f, 0.f, 0.f, 0.f);

    for (int p = 0; p < npair; ++p) {
        const float4* Wsrc = (const float4*)Ws[p];
        #pragma unroll
        for (int i = 0; i < 16; ++i) sW[tid + i*256] = Wsrc[tid + i*256];
        const float4* Xsrc = (const float4*)(Xs[p] + (size_t)row0 * EMB);
        #pragma unroll
        for (int i = 0; i < 8; ++i) {
            int idx = tid + i*256;                       // 0..2047
            float4 v = Xsrc[idx];
            ((float4*)(sX + (idx >> 5) * 132))[idx & 31] = v;
        }
        __syncthreads();

        #pragma unroll 8
        for (int k = 0; k < 128; ++k) {
            float xa = sX[r*132 + k];
            float xb = sX[(r+32)*132 + k];
            #pragma unroll
            for (int j = 0; j < 4; ++j) {
                float4 w = sW[k*32 + cg + 8*j];
                acc[0][j].x = fmaf(xa, w.x, acc[0][j].x);
                acc[0][j].y = fmaf(xa, w.y, acc[0][j].y);
                acc[0][j].z = fmaf(xa, w.z, acc[0][j].z);
                acc[0][j].w = fmaf(xa, w.w, acc[0][j].w);
                acc[1][j].x = fmaf(xb, w.x, acc[1][j].x);
                acc[1][j].y = fmaf(xb, w.y, acc[1][j].y);
                acc[1][j].z = fmaf(xb, w.z, acc[1][j].z);
                acc[1][j].w = fmaf(xb, w.w, acc[1][j].w);
            }
        }
        __syncthreads();
    }

    float4 bv[4];
    #pragma unroll
    for (int j = 0; j < 4; ++j) bv[j] = make_float4(0.f, 0.f, 0.f, 0.f);
    if (bias0 != nullptr) {
        #pragma unroll
        for (int j = 0; j < 4; ++j) {
            float4 a = ((const float4*)bias0)[cg + 8*j];
            float4 b = ((const float4*)bias1)[cg + 8*j];
            bv[j] = make_float4(a.x + b.x, a.y + b.y, a.z + b.z, a.w + b.w);
        }
    }

    #pragma unroll
    for (int a = 0; a < 2; ++a) {
        size_t row = (size_t)row0 + r + 32*a;
        float4* yr = (float4*)(Y + row * EMB);
        #pragma unroll
        for (int j = 0; j < 4; ++j) {
            float4 o = acc[a][j];
            o.x += bv[j].x; o.y += bv[j].y; o.z += bv[j].z; o.w += bv[j].w;
            yr[cg + 8*j] = o;
        }
    }
}

// ---------------------------------------------------------------------------
// Dual-MHA flash-style kernel. grid = (8 qtiles, 32 batches, 2 mhas), 256 thr.
// Thread mapping: hp = tid>>6 (head pair), ql = tid&63 (query in tile).
// Warp = 32 consecutive ql with same hp -> K/V smem reads are pure broadcasts.
// Mask stored transposed in smem -> conflict-free per-key read.
// ---------------------------------------------------------------------------
__global__ __launch_bounds__(256, 2)
void attn_kernel(const float* __restrict__ mask)
{
    extern __shared__ float sm[];
    float* sK  = sm;                 // [64][128]
    float* sV  = sm + 64*128;        // [64][128]
    float* sMT = sV + 64*128;        // [64 keys][64 queries]

    const int tid = threadIdx.x;
    const int b   = blockIdx.y;
    const int q0  = blockIdx.x * 64;
    const int mha = blockIdx.z;

    const float* Kg = mha ? g_Ke : g_K;
    const float* Vg = mha ? g_Ve : g_V;
    float*       Og = mha ? g_O2 : g_O1;

    const int hp = tid >> 6;   // 0..3 -> heads 2hp, 2hp+1 -> cols hp*32 + hh*16
    const int ql = tid & 63;

    // load q (scaled by 1/sqrt(16) = 0.25 to fold the score scale)
    float4 qreg[2][4];
    {
        const float4* qsrc = (const float4*)(g_Q + ((size_t)b*SEQ + q0 + ql)*EMB + hp*32);
        #pragma unroll
        for (int hh = 0; hh < 2; ++hh)
            #pragma unroll
            for (int i = 0; i < 4; ++i) {
                float4 v = qsrc[hh*4 + i];
                v.x *= 0.25f; v.y *= 0.25f; v.z *= 0.25f; v.w *= 0.25f;
                qreg[hh][i] = v;
            }
    }

    float  mrun[2] = {-1e30f, -1e30f};
    float  lrun[2] = {0.f, 0.f};
    float4 acc[2][4];
    #pragma unroll
    for (int hh = 0; hh < 2; ++hh)
        #pragma unroll
        for (int i = 0; i < 4; ++i) acc[hh][i] = make_float4(0.f, 0.f, 0.f, 0.f);

    const float* Kb = Kg + (size_t)b*SEQ*EMB;
    const float* Vb = Vg + (size_t)b*SEQ*EMB;
    const float* Mb = mask + ((size_t)b*SEQ + q0)*SEQ;

    for (int kt = 0; kt < 8; ++kt) {
        const int k0 = kt * 64;
        // --- load K, V tiles (coalesced float4) ---
        {
            const float4* src = (const float4*)(Kb + (size_t)k0*EMB);
            float4* dst = (float4*)sK;
            #pragma unroll
            for (int i = 0; i < 8; ++i) dst[tid + i*256] = src[tid + i*256];
            src = (const float4*)(Vb + (size_t)k0*EMB);
            dst = (float4*)sV;
            #pragma unroll
            for (int i = 0; i < 8; ++i) dst[tid + i*256] = src[tid + i*256];
            // --- mask transpose: sMT[key][query] ---
            const int mq = tid >> 2;       // 0..63 query
            const int mg = tid & 3;        // 16 keys each
            const float4* msrc = (const float4*)(Mb + (size_t)mq*SEQ + k0 + mg*16);
            #pragma unroll
            for (int i = 0; i < 4; ++i) {
                float4 v = msrc[i];
                int j = mg*16 + i*4;
                sMT[(j+0)*64 + mq] = v.x;
                sMT[(j+1)*64 + mq] = v.y;
                sMT[(j+2)*64 + mq] = v.z;
                sMT[(j+3)*64 + mq] = v.w;
            }
        }
        __syncthreads();

        for (int j = 0; j < 64; ++j) {
            const float  mk   = sMT[j*64 + ql];
            const float4* krow = (const float4*)(sK + j*EMB + hp*32);
            const float4* vrow = (const float4*)(sV + j*EMB + hp*32);
            #pragma unroll
            for (int hh = 0; hh < 2; ++hh) {
                float4 ka = krow[hh*4+0], kb2 = krow[hh*4+1], kc = krow[hh*4+2], kd = krow[hh*4+3];
                float s =
                    qreg[hh][0].x*ka.x  + qreg[hh][0].y*ka.y  + qreg[hh][0].z*ka.z  + qreg[hh][0].w*ka.w +
                    qreg[hh][1].x*kb2.x + qreg[hh][1].y*kb2.y + qreg[hh][1].z*kb2.z + qreg[hh][1].w*kb2.w +
                    qreg[hh][2].x*kc.x  + qreg[hh][2].y*kc.y  + qreg[hh][2].z*kc.z  + qreg[hh][2].w*kc.w +
                    qreg[hh][3].x*kd.x  + qreg[hh][3].y*kd.y  + qreg[hh][3].z*kd.z  + qreg[hh][3].w*kd.w;
                s += mk;
                float4 va = vrow[hh*4+0], vb2 = vrow[hh*4+1], vc = vrow[hh*4+2], vd = vrow[hh*4+3];
                if (s <= mrun[hh]) {
                    float e = __expf(s - mrun[hh]);
                    lrun[hh] += e;
                    acc[hh][0].x += e*va.x;  acc[hh][0].y += e*va.y;  acc[hh][0].z += e*va.z;  acc[hh][0].w += e*va.w;
                    acc[hh][1].x += e*vb2.x; acc[hh][1].y += e*vb2.y; acc[hh][1].z += e*vb2.z; acc[hh][1].w += e*vb2.w;
                    acc[hh][2].x += e*vc.x;  acc[hh][2].y += e*vc.y;  acc[hh][2].z += e*vc.z;  acc[hh][2].w += e*vc.w;
                    acc[hh][3].x += e*vd.x;  acc[hh][3].y += e*vd.y;  acc[hh][3].z += e*vd.z;  acc[hh][3].w += e*vd.w;
                } else {
                    float c = __expf(mrun[hh] - s);
                    mrun[hh] = s;
                    lrun[hh] = fmaf(lrun[hh], c, 1.0f);
                    acc[hh][0].x = fmaf(acc[hh][0].x, c, va.x);  acc[hh][0].y = fmaf(acc[hh][0].y, c, va.y);
                    acc[hh][0].z = fmaf(acc[hh][0].z, c, va.z);  acc[hh][0].w = fmaf(acc[hh][0].w, c, va.w);
                    acc[hh][1].x = fmaf(acc[hh][1].x, c, vb2.x); acc[hh][1].y = fmaf(acc[hh][1].y, c, vb2.y);
                    acc[hh][1].z = fmaf(acc[hh][1].z, c, vb2.z); acc[hh][1].w = fmaf(acc[hh][1].w, c, vb2.w);
                    acc[hh][2].x = fmaf(acc[hh][2].x, c, vc.x);  acc[hh][2].y = fmaf(acc[hh][2].y, c, vc.y);
                    acc[hh][2].z = fmaf(acc[hh][2].z, c, vc.z);  acc[hh][2].w = fmaf(acc[hh][2].w, c, vc.w);
                    acc[hh][3].x = fmaf(acc[hh][3].x, c, vd.x);  acc[hh][3].y = fmaf(acc[hh][3].y, c, vd.y);
                    acc[hh][3].z = fmaf(acc[hh][3].z, c, vd.z);  acc[hh][3].w = fmaf(acc[hh][3].w, c, vd.w);
                }
            }
        }
        __syncthreads();
    }

    // write out: out[b][q0+ql][hp*32 + hh*16 + i] = acc / l
    float4* od = (float4*)(Og + ((size_t)b*SEQ + q0 + ql)*EMB + hp*32);
    #pragma unroll
    for (int hh = 0; hh < 2; ++hh) {
        float inv = 1.0f / lrun[hh];
        #pragma unroll
        for (int i = 0; i < 4; ++i) {
            float4 o = acc[hh][i];
            o.x *= inv; o.y *= inv; o.z *= inv; o.w *= inv;
            od[hh*4 + i] = o;
        }
    }
}

// ---------------------------------------------------------------------------
// Final: logits = 10*tanh((MH @ (nodes+graph)^T)/sqrt(128)) + mask; softmax(n).
// grid = (16 qtiles of 32, 32 batches), 256 threads.
// ---------------------------------------------------------------------------
__global__ __launch_bounds__(256)
void final_kernel(const float* __restrict__ nodes, const float* __restrict__ graph,
                  const float* __restrict__ mask, float* __restrict__ out)
{
    extern __shared__ float sm[];
    float* sMH  = sm;               // [32][132]
    float* sShk = sMH + 32*132;     // [64][132]
    float* sLg  = sShk + 64*132;    // [32][516]

    const int tid = threadIdx.x;
    const int b   = blockIdx.y;
    const int q0  = blockIdx.x * 32;

    // load MH tile
    {
        const float4* msrc = (const float4*)(g_MH + ((size_t)b*SEQ + q0)*EMB);
        #pragma unroll
        for (int i = 0; i < 4; ++i) {
            int idx = tid + i*256;                      // 0..1023
            float4 v = msrc[idx];
            ((float4*)(sMH + (idx >> 5)*132))[idx & 31] = v;
        }
    }

    const int q = tid >> 3;   // 0..31
    const int g = tid & 7;    // 0..7
    const float* Mrow = mask + ((size_t)b*SEQ + q0 + q)*SEQ;

    for (int nt = 0; nt < 8; ++nt) {
        const int n0 = nt * 64;
        __syncthreads();   // protect sShk (and cover first-iter sMH load)
        {
            const float4* ns = (const float4*)(nodes + ((size_t)b*SEQ + n0)*EMB);
            const float4* gs = (const float4*)(graph + ((size_t)b*SEQ + n0)*EMB);
            #pragma unroll
            for (int i = 0; i < 8; ++i) {
                int idx = tid + i*256;                  // 0..2047
                float4 a = ns[idx], c = gs[idx];
                a.x += c.x; a.y += c.y; a.z += c.z; a.w += c.w;
                ((float4*)(sShk + (idx >> 5)*132))[idx & 31] = a;
            }
        }
        __syncthreads();

        float acc[8];
        #pragma unroll
        for (int j = 0; j < 8; ++j) acc[j] = 0.f;
        const float4* mrow = (const float4*)(sMH + q*132);
        #pragma unroll 4
        for (int k4 = 0; k4 < 32; ++k4) {
            float4 m4 = mrow[k4];
            #pragma unroll
            for (int j = 0; j < 8; ++j) {
                float4 s4 = ((const float4*)(sShk + (g + 8*j)*132))[k4];
                acc[j] += m4.x*s4.x + m4.y*s4.y + m4.z*s4.z + m4.w*s4.w;
            }
        }
        #pragma unroll
        for (int j = 0; j < 8; ++j) {
            int n = n0 + g + 8*j;
            float val = 10.0f * tanhf(acc[j] * 0.088388347648318447f) + Mrow[n];
            sLg[q*516 + n] = val;
        }
    }
    __syncthreads();

    // phase 2: row softmax, coalesced writes
    const int wid = tid >> 5, lane = tid & 31;
    #pragma unroll
    for (int rr = 0; rr < 4; ++rr) {
        const int row = wid*4 + rr;
        const float* lrow = sLg + row*516;
        float vbuf[16];
        float mx = -1e30f;
        #pragma unroll
        for (int i = 0; i < 16; ++i) {
            float v = lrow[lane + 32*i];
            vbuf[i] = v;
            mx = fmaxf(mx, v);
        }
        #pragma unroll
        for (int off = 16; off > 0; off >>= 1)
            mx = fmaxf(mx, __shfl_xor_sync(0xffffffffu, mx, off));
        float ssum = 0.f;
        #pragma unroll
        for (int i = 0; i < 16; ++i) {
            float e = __expf(vbuf[i] - mx);
            vbuf[i] = e;
            ssum += e;
        }
        #pragma unroll
        for (int off = 16; off > 0; off >>= 1)
            ssum += __shfl_xor_sync(0xffffffffu, ssum, off);
        float inv = 1.0f / ssum;
        float* orow = out + ((size_t)b*SEQ + q0 + row)*SEQ;
        #pragma unroll
        for (int i = 0; i < 16; ++i)
            orow[lane + 32*i] = vbuf[i] * inv;
    }
}

// ---------------------------------------------------------------------------
// Launch
// ---------------------------------------------------------------------------
extern "C" void kernel_launch(void* const* d_in, const int* in_sizes, int n_in,
                              void* d_out, int out_size)
{
    const float* nodes = (const float*)d_in[0];
    const float* graph = (const float*)d_in[1];
    const float* q1    = (const float*)d_in[2];
    const float* fg    = (const float*)d_in[3];
    const float* ln    = (const float*)d_in[4];
    const float* lg    = (const float*)d_in[5];
    const float* mask  = (const float*)d_in[6];
    const float* Wqf   = (const float*)d_in[7];
    const float* Wql   = (const float*)d_in[8];
    const float* Wk    = (const float*)d_in[9];
    const float* Wv    = (const float*)d_in[10];
    const float* Wqfe  = (const float*)d_in[11];
    const float* Wqle  = (const float*)d_in[12];
    const float* Wke   = (const float*)d_in[13];
    const float* Wve   = (const float*)d_in[14];
    const float* Wc1   = (const float*)d_in[15];
    const float* bc1   = (const float*)d_in[16];
    const float* Wc2   = (const float*)d_in[17];
    const float* bc2   = (const float*)d_in[18];
    float* out = (float*)d_out;

    (void)in_sizes; (void)n_in; (void)out_size;

    cudaFuncSetAttribute(gemm128,      cudaFuncAttributeMaxDynamicSharedMemorySize, GEMM_SMEM);
    cudaFuncSetAttribute(attn_kernel,  cudaFuncAttributeMaxDynamicSharedMemorySize, ATTN_SMEM);
    cudaFuncSetAttribute(final_kernel, cudaFuncAttributeMaxDynamicSharedMemorySize, FINAL_SMEM);

    const int gemm_blocks = (NB*SEQ) / 64;   // 256

    // Q = q1@Wqf + ln@Wql + fg@Wqfe + lg@Wqle
    gemm128<<<gemm_blocks, 256, GEMM_SMEM>>>(JOB_Q, q1, ln, fg, lg,
                                             Wqf, Wql, Wqfe, Wqle, nullptr, nullptr);
    gemm128<<<gemm_blocks, 256, GEMM_SMEM>>>(JOB_K,  nodes, nullptr, nullptr, nullptr,
                                             Wk,  nullptr, nullptr, nullptr, nullptr, nullptr);
    gemm128<<<gemm_blocks, 256, GEMM_SMEM>>>(JOB_V,  nodes, nullptr, nullptr, nullptr,
                                             Wv,  nullptr, nullptr, nullptr, nullptr, nullptr);
    gemm128<<<gemm_blocks, 256, GEMM_SMEM>>>(JOB_KE, graph, nullptr, nullptr, nullptr,
                                             Wke, nullptr, nullptr, nullptr, nullptr, nullptr);
    gemm128<<<gemm_blocks, 256, GEMM_SMEM>>>(JOB_VE, graph, nullptr, nullptr, nullptr,
                                             Wve, nullptr, nullptr, nullptr, nullptr, nullptr);

    attn_kernel<<<dim3(8, 32, 2), 256, ATTN_SMEM>>>(mask);

    // MH = O1@Wc1 + O2@Wc2 + (bc1 + bc2)
    gemm128<<<gemm_blocks, 256, GEMM_SMEM>>>(JOB_MH, nullptr, nullptr, nullptr, nullptr,
                                             Wc1, Wc2, nullptr, nullptr, bc1, bc2);

    final_kernel<<<dim3(16, 32), 256, FINAL_SMEM>>>(nodes, graph, mask, out);
}

// round 4
// speedup vs baseline: 1.1353x; 1.1353x over previous
#include <cuda_runtime.h>
#include <math.h>
#include <stdint.h>

// Problem constants (fixed shapes)
#define NB   32
#define SEQ  512
#define EMB  128
#define BSE  (NB*SEQ*EMB)

typedef unsigned long long ull;

// ---------------------------------------------------------------------------
// Packed fp32x2 helpers (Blackwell FFMA2 — only reachable via PTX)
// ---------------------------------------------------------------------------
__device__ __forceinline__ ull ffma2(ull a, ull b, ull c) {
    ull d;
    asm("fma.rn.f32x2 %0, %1, %2, %3;" : "=l"(d) : "l"(a), "l"(b), "l"(c));
    return d;
}
__device__ __forceinline__ ull pack2(float lo, float hi) {
    ull d;
    asm("mov.b64 %0, {%1, %2};" : "=l"(d) : "f"(lo), "f"(hi));
    return d;
}
__device__ __forceinline__ float2 unpack2(ull v) {
    float lo, hi;
    asm("mov.b64 {%0, %1}, %2;" : "=f"(lo), "=f"(hi) : "l"(v));
    return make_float2(lo, hi);
}

// ---------------------------------------------------------------------------
// Scratch (static device arrays; no allocations allowed)
// ---------------------------------------------------------------------------
__device__ float g_Q [BSE];
__device__ float g_K [BSE];
__device__ float g_V [BSE];
__device__ float g_Ke[BSE];
__device__ float g_Ve[BSE];
__device__ float g_O1[BSE];
__device__ float g_O2[BSE];
__device__ float g_MH[BSE];

// dynamic smem sizes
constexpr int GEMM_SMEM  = 64*132*4 + 128*32*16;              // 99328 B
constexpr int ATTN_SMEM  = (64*128 + 64*128 + 64*64) * 4;     // 81920 B
constexpr int FINAL_SMEM = (32*132 + 64*132 + 32*516) * 4;    // 116736 B

// ---------------------------------------------------------------------------
// GEMM body: Y[16384,128] = sum_p Xp[16384,128] @ Wp[128,128] (+bias0+bias1)
// Block: 64 rows x 128 cols, 256 threads, each thread 2 rows x 16 cols.
// Inner loop uses packed f32x2 FMAs (16 FFMA2/k instead of 32 FFMA/k).
// ---------------------------------------------------------------------------
__device__ __forceinline__ void gemm_body(
    const float* const* Xs, const float* const* Ws, int npair,
    const float* bias0, const float* bias1, float* Y)
{
    extern __shared__ float sm[];
    float*  sX = sm;                         // [64][132]
    float4* sW = (float4*)(sm + 64*132);     // [128][32] float4

    const int tid  = threadIdx.x;
    const int row0 = blockIdx.x * 64;
    const int r    = tid >> 3;   // 0..31
    const int cg   = tid & 7;    // cols 4*(cg+8j)+0..3

    ull acc2[2][8];
    #pragma unroll
    for (int a = 0; a < 2; ++a)
        #pragma unroll
        for (int j = 0; j < 8; ++j) acc2[a][j] = 0ull;

    for (int p = 0; p < npair; ++p) {
        const float4* Wsrc = (const float4*)Ws[p];
        #pragma unroll
        for (int i = 0; i < 16; ++i) sW[tid + i*256] = Wsrc[tid + i*256];
        const float4* Xsrc = (const float4*)(Xs[p] + (size_t)row0 * EMB);
        #pragma unroll
        for (int i = 0; i < 8; ++i) {
            int idx = tid + i*256;                       // 0..2047
            float4 v = Xsrc[idx];
            ((float4*)(sX + (idx >> 5) * 132))[idx & 31] = v;
        }
        __syncthreads();

        #pragma unroll 8
        for (int k = 0; k < 128; ++k) {
            float xa = sX[r*132 + k];
            float xb = sX[(r+32)*132 + k];
            ull xa2 = pack2(xa, xa);
            ull xb2 = pack2(xb, xb);
            const ulonglong2* w2 = (const ulonglong2*)(sW + k*32);
            #pragma unroll
            for (int j = 0; j < 4; ++j) {
                ulonglong2 w = w2[cg + 8*j];
                acc2[0][2*j  ] = ffma2(xa2, w.x, acc2[0][2*j  ]);
                acc2[0][2*j+1] = ffma2(xa2, w.y, acc2[0][2*j+1]);
                acc2[1][2*j  ] = ffma2(xb2, w.x, acc2[1][2*j  ]);
                acc2[1][2*j+1] = ffma2(xb2, w.y, acc2[1][2*j+1]);
            }
        }
        __syncthreads();
    }

    float4 bv[4];
    #pragma unroll
    for (int j = 0; j < 4; ++j) bv[j] = make_float4(0.f, 0.f, 0.f, 0.f);
    if (bias0 != nullptr) {
        #pragma unroll
        for (int j = 0; j < 4; ++j) {
            float4 a = ((const float4*)bias0)[cg + 8*j];
            float4 b = ((const float4*)bias1)[cg + 8*j];
            bv[j] = make_float4(a.x + b.x, a.y + b.y, a.z + b.z, a.w + b.w);
        }
    }

    #pragma unroll
    for (int a = 0; a < 2; ++a) {
        size_t row = (size_t)row0 + r + 32*a;
        float4* yr = (float4*)(Y + row * EMB);
        #pragma unroll
        for (int j = 0; j < 4; ++j) {
            float2 lo = unpack2(acc2[a][2*j]);
            float2 hi = unpack2(acc2[a][2*j+1]);
            float4 o = make_float4(lo.x + bv[j].x, lo.y + bv[j].y,
                                   hi.x + bv[j].z, hi.y + bv[j].w);
            yr[cg + 8*j] = o;
        }
    }
}

// Merged projection GEMMs: grid (256, 5). y: 0=Q(4 pairs), 1=K, 2=V, 3=Ke, 4=Ve.
__global__ __launch_bounds__(256)
void proj_gemm(const float* __restrict__ q1,  const float* __restrict__ ln,
               const float* __restrict__ fg,  const float* __restrict__ lg,
               const float* __restrict__ Wqf, const float* __restrict__ Wql,
               const float* __restrict__ Wqfe,const float* __restrict__ Wqle,
               const float* __restrict__ nodes, const float* __restrict__ graph,
               const float* __restrict__ Wk,  const float* __restrict__ Wv,
               const float* __restrict__ Wke, const float* __restrict__ Wve)
{
    const float* Xs[4];
    const float* Ws[4];
    float* Y;
    int npair;
    switch (blockIdx.y) {
        case 0: npair = 4; Xs[0]=q1; Xs[1]=ln; Xs[2]=fg; Xs[3]=lg;
                Ws[0]=Wqf; Ws[1]=Wql; Ws[2]=Wqfe; Ws[3]=Wqle; Y=g_Q; break;
        case 1: npair = 1; Xs[0]=nodes; Ws[0]=Wk;  Y=g_K;  break;
        case 2: npair = 1; Xs[0]=nodes; Ws[0]=Wv;  Y=g_V;  break;
        case 3: npair = 1; Xs[0]=graph; Ws[0]=Wke; Y=g_Ke; break;
        default:npair = 1; Xs[0]=graph; Ws[0]=Wve; Y=g_Ve; break;
    }
    gemm_body(Xs, Ws, npair, nullptr, nullptr, Y);
}

// MH = O1@Wc1 + O2@Wc2 + (bc1 + bc2)
__global__ __launch_bounds__(256)
void mh_gemm(const float* __restrict__ Wc1, const float* __restrict__ Wc2,
             const float* __restrict__ bc1, const float* __restrict__ bc2)
{
    const float* Xs[2] = { g_O1, g_O2 };
    const float* Ws[2] = { Wc1, Wc2 };
    gemm_body(Xs, Ws, 2, bc1, bc2, g_MH);
}

// ---------------------------------------------------------------------------
// Dual-MHA flash-style kernel. grid = (8 qtiles, 32 batches, 2 mhas), 256 thr.
// Thread mapping: h = tid>>5 (one warp per head), lane owns queries
// {lane, lane+32} of the 64-query tile -> K/V smem rows loaded ONCE per thread
// and reused for 2 queries (halves LDS vs 1q/2h mapping); reads are
// warp-uniform broadcasts. All dot/AXPY math in packed f32x2.
// ---------------------------------------------------------------------------
__global__ __launch_bounds__(256, 2)
void attn_kernel(const float* __restrict__ mask)
{
    extern __shared__ float sm[];
    float* sK  = sm;                 // [64][128]
    float* sV  = sm + 64*128;        // [64][128]
    float* sMT = sV + 64*128;        // [64 keys][64 queries]

    const int tid = threadIdx.x;
    const int b   = blockIdx.y;
    const int q0  = blockIdx.x * 64;
    const int mha = blockIdx.z;

    const float* Kg = mha ? g_Ke : g_K;
    const float* Vg = mha ? g_Ve : g_V;
    float*       Og = mha ? g_O2 : g_O1;

    const int h    = tid >> 5;   // 0..7 head
    const int lane = tid & 31;   // query a = lane, query b = lane+32

    // load q for both queries (scaled by 1/sqrt(16) = 0.25)
    ull qa2[8], qb2[8];
    {
        const float4* pa = (const float4*)(g_Q + ((size_t)b*SEQ + q0 + lane)*EMB + h*16);
        const float4* pb = (const float4*)(g_Q + ((size_t)b*SEQ + q0 + lane + 32)*EMB + h*16);
        #pragma unroll
        for (int i = 0; i < 4; ++i) {
            float4 va = pa[i], vb = pb[i];
            qa2[2*i  ] = pack2(va.x*0.25f, va.y*0.25f);
            qa2[2*i+1] = pack2(va.z*0.25f, va.w*0.25f);
            qb2[2*i  ] = pack2(vb.x*0.25f, vb.y*0.25f);
            qb2[2*i+1] = pack2(vb.z*0.25f, vb.w*0.25f);
        }
    }

    float ma = -1e30f, mb2 = -1e30f;
    float la = 0.f,    lb = 0.f;
    ull aa2[8], ab2[8];
    #pragma unroll
    for (int i = 0; i < 8; ++i) { aa2[i] = 0ull; ab2[i] = 0ull; }

    const float* Kb = Kg + (size_t)b*SEQ*EMB;
    const float* Vb = Vg + (size_t)b*SEQ*EMB;
    const float* Mb = mask + ((size_t)b*SEQ + q0)*SEQ;

    for (int kt = 0; kt < 8; ++kt) {
        const int k0 = kt * 64;
        // --- load K, V tiles (coalesced float4) ---
        {
            const float4* src = (const float4*)(Kb + (size_t)k0*EMB);
            float4* dst = (float4*)sK;
            #pragma unroll
            for (int i = 0; i < 8; ++i) dst[tid + i*256] = src[tid + i*256];
            src = (const float4*)(Vb + (size_t)k0*EMB);
            dst = (float4*)sV;
            #pragma unroll
            for (int i = 0; i < 8; ++i) dst[tid + i*256] = src[tid + i*256];
            // --- mask transpose: sMT[key][query] ---
            const int mq = tid >> 2;       // 0..63 query
            const int mg = tid & 3;        // 16 keys each
            const float4* msrc = (const float4*)(Mb + (size_t)mq*SEQ + k0 + mg*16);
            #pragma unroll
            for (int i = 0; i < 4; ++i) {
                float4 v = msrc[i];
                int j = mg*16 + i*4;
                sMT[(j+0)*64 + mq] = v.x;
                sMT[(j+1)*64 + mq] = v.y;
                sMT[(j+2)*64 + mq] = v.z;
                sMT[(j+3)*64 + mq] = v.w;
            }
        }
        __syncthreads();

        for (int j = 0; j < 64; ++j) {
            const ulonglong2* kr = (const ulonglong2*)(sK + j*EMB + h*16);
            ulonglong2 k01 = kr[0], k23 = kr[1], k45 = kr[2], k67 = kr[3];

            ull sa2 = 0ull, sb2 = 0ull;
            sa2 = ffma2(qa2[0], k01.x, sa2);  sb2 = ffma2(qb2[0], k01.x, sb2);
            sa2 = ffma2(qa2[1], k01.y, sa2);  sb2 = ffma2(qb2[1], k01.y, sb2);
            sa2 = ffma2(qa2[2], k23.x, sa2);  sb2 = ffma2(qb2[2], k23.x, sb2);
            sa2 = ffma2(qa2[3], k23.y, sa2);  sb2 = ffma2(qb2[3], k23.y, sb2);
            sa2 = ffma2(qa2[4], k45.x, sa2);  sb2 = ffma2(qb2[4], k45.x, sb2);
            sa2 = ffma2(qa2[5], k45.y, sa2);  sb2 = ffma2(qb2[5], k45.y, sb2);
            sa2 = ffma2(qa2[6], k67.x, sa2);  sb2 = ffma2(qb2[6], k67.x, sb2);
            sa2 = ffma2(qa2[7], k67.y, sa2);  sb2 = ffma2(qb2[7], k67.y, sb2);

            float2 fa = unpack2(sa2);
            float2 fb = unpack2(sb2);
            float sa = fa.x + fa.y + sMT[j*64 + lane];
            float sb = fb.x + fb.y + sMT[j*64 + lane + 32];

            const ulonglong2* vr = (const ulonglong2*)(sV + j*EMB + h*16);
            ulonglong2 v01 = vr[0], v23 = vr[1], v45 = vr[2], v67 = vr[3];

            // online softmax update, query a
            if (sa <= ma) {
                float e = __expf(sa - ma);
                la += e;
                ull e2 = pack2(e, e);
                aa2[0] = ffma2(e2, v01.x, aa2[0]); aa2[1] = ffma2(e2, v01.y, aa2[1]);
                aa2[2] = ffma2(e2, v23.x, aa2[2]); aa2[3] = ffma2(e2, v23.y, aa2[3]);
                aa2[4] = ffma2(e2, v45.x, aa2[4]); aa2[5] = ffma2(e2, v45.y, aa2[5]);
                aa2[6] = ffma2(e2, v67.x, aa2[6]); aa2[7] = ffma2(e2, v67.y, aa2[7]);
            } else {
                float c = __expf(ma - sa);
                ma = sa;
                la = fmaf(la, c, 1.0f);
                ull c2 = pack2(c, c);
                aa2[0] = ffma2(aa2[0], c2, v01.x); aa2[1] = ffma2(aa2[1], c2, v01.y);
                aa2[2] = ffma2(aa2[2], c2, v23.x); aa2[3] = ffma2(aa2[3], c2, v23.y);
                aa2[4] = ffma2(aa2[4], c2, v45.x); aa2[5] = ffma2(aa2[5], c2, v45.y);
                aa2[6] = ffma2(aa2[6], c2, v67.x); aa2[7] = ffma2(aa2[7], c2, v67.y);
            }
            // query b
            if (sb <= mb2) {
                float e = __expf(sb - mb2);
                lb += e;
                ull e2 = pack2(e, e);
                ab2[0] = ffma2(e2, v01.x, ab2[0]); ab2[1] = ffma2(e2, v01.y, ab2[1]);
                ab2[2] = ffma2(e2, v23.x, ab2[2]); ab2[3] = ffma2(e2, v23.y, ab2[3]);
                ab2[4] = ffma2(e2, v45.x, ab2[4]); ab2[5] = ffma2(e2, v45.y, ab2[5]);
                ab2[6] = ffma2(e2, v67.x, ab2[6]); ab2[7] = ffma2(e2, v67.y, ab2[7]);
            } else {
                float c = __expf(mb2 - sb);
                mb2 = sb;
                lb = fmaf(lb, c, 1.0f);
                ull c2 = pack2(c, c);
                ab2[0] = ffma2(ab2[0], c2, v01.x); ab2[1] = ffma2(ab2[1], c2, v01.y);
                ab2[2] = ffma2(ab2[2], c2, v23.x); ab2[3] = ffma2(ab2[3], c2, v23.y);
                ab2[4] = ffma2(ab2[4], c2, v45.x); ab2[5] = ffma2(ab2[5], c2, v45.y);
                ab2[6] = ffma2(ab2[6], c2, v67.x); ab2[7] = ffma2(ab2[7], c2, v67.y);
            }
        }
        __syncthreads();
    }

    // write out both queries
    {
        float inv = 1.0f / la;
        float4* od = (float4*)(Og + ((size_t)b*SEQ + q0 + lane)*EMB + h*16);
        #pragma unroll
        for (int i = 0; i < 4; ++i) {
            float2 lo = unpack2(aa2[2*i]);
            float2 hi = unpack2(aa2[2*i+1]);
            od[i] = make_float4(lo.x*inv, lo.y*inv, hi.x*inv, hi.y*inv);
        }
    }
    {
        float inv = 1.0f / lb;
        float4* od = (float4*)(Og + ((size_t)b*SEQ + q0 + lane + 32)*EMB + h*16);
        #pragma unroll
        for (int i = 0; i < 4; ++i) {
            float2 lo = unpack2(ab2[2*i]);
            float2 hi = unpack2(ab2[2*i+1]);
            od[i] = make_float4(lo.x*inv, lo.y*inv, hi.x*inv, hi.y*inv);
        }
    }
}

// ---------------------------------------------------------------------------
// Final: logits = 10*tanh((MH @ (nodes+graph)^T)/sqrt(128)) + mask; softmax(n).
// grid = (16 qtiles of 32, 32 batches), 256 threads. Packed f32x2 dot-products,
// exp-based tanh (10 - 20/(e^{2x}+1)): exact saturation at +-inf, rel err ~1e-7.
// ---------------------------------------------------------------------------
__global__ __launch_bounds__(256)
void final_kernel(const float* __restrict__ nodes, const float* __restrict__ graph,
                  const float* __restrict__ mask, float* __restrict__ out)
{
    extern __shared__ float sm[];
    float* sMH  = sm;               // [32][132]
    float* sShk = sMH + 32*132;     // [64][132]
    float* sLg  = sShk + 64*132;    // [32][516]

    const int tid = threadIdx.x;
    const int b   = blockIdx.y;
    const int q0  = blockIdx.x * 32;

    // load MH tile
    {
        const float4* msrc = (const float4*)(g_MH + ((size_t)b*SEQ + q0)*EMB);
        #pragma unroll
        for (int i = 0; i < 4; ++i) {
            int idx = tid + i*256;                      // 0..1023
            float4 v = msrc[idx];
            ((float4*)(sMH + (idx >> 5)*132))[idx & 31] = v;
        }
    }

    const int q = tid >> 3;   // 0..31
    const int g = tid & 7;    // 0..7
    const float* Mrow = mask + ((size_t)b*SEQ + q0 + q)*SEQ;

    for (int nt = 0; nt < 8; ++nt) {
        const int n0 = nt * 64;
        __syncthreads();   // protect sShk (and cover first-iter sMH load)
        {
            const float4* ns = (const float4*)(nodes + ((size_t)b*SEQ + n0)*EMB);
            const float4* gs = (const float4*)(graph + ((size_t)b*SEQ + n0)*EMB);
            #pragma unroll
            for (int i = 0; i < 8; ++i) {
                int idx = tid + i*256;                  // 0..2047
                float4 a = ns[idx], c = gs[idx];
                a.x += c.x; a.y += c.y; a.z += c.z; a.w += c.w;
                ((float4*)(sShk + (idx >> 5)*132))[idx & 31] = a;
            }
        }
        __syncthreads();

        ull acc2[8];
        #pragma unroll
        for (int j = 0; j < 8; ++j) acc2[j] = 0ull;
        const ulonglong2* mrow2 = (const ulonglong2*)(sMH + q*132);
        #pragma unroll 4
        for (int k4 = 0; k4 < 32; ++k4) {
            ulonglong2 m2 = mrow2[k4];
            #pragma unroll
            for (int j = 0; j < 8; ++j) {
                ulonglong2 s2 = ((const ulonglong2*)(sShk + (g + 8*j)*132))[k4];
                acc2[j] = ffma2(m2.x, s2.x, acc2[j]);
                acc2[j] = ffma2(m2.y, s2.y, acc2[j]);
            }
        }
        #pragma unroll
        for (int j = 0; j < 8; ++j) {
            int n = n0 + g + 8*j;
            float2 f = unpack2(acc2[j]);
            float a = f.x + f.y;
            // 10*tanh(a*c) = 10 - 20/(exp(2*c*a)+1)
            float ex = __expf(a * 0.17677669529663689f);
            float val = 10.0f - __fdividef(20.0f, ex + 1.0f) + Mrow[n];
            sLg[q*516 + n] = val;
        }
    }
    __syncthreads();

    // phase 2: row softmax, coalesced writes
    const int wid = tid >> 5, lane = tid & 31;
    #pragma unroll
    for (int rr = 0; rr < 4; ++rr) {
        const int row = wid*4 + rr;
        const float* lrow = sLg + row*516;
        float vbuf[16];
        float mx = -1e30f;
        #pragma unroll
        for (int i = 0; i < 16; ++i) {
            float v = lrow[lane + 32*i];
            vbuf[i] = v;
            mx = fmaxf(mx, v);
        }
        #pragma unroll
        for (int off = 16; off > 0; off >>= 1)
            mx = fmaxf(mx, __shfl_xor_sync(0xffffffffu, mx, off));
        float ssum = 0.f;
        #pragma unroll
        for (int i = 0; i < 16; ++i) {
            float e = __expf(vbuf[i] - mx);
            vbuf[i] = e;
            ssum += e;
        }
        #pragma unroll
        for (int off = 16; off > 0; off >>= 1)
            ssum += __shfl_xor_sync(0xffffffffu, ssum, off);
        float inv = 1.0f / ssum;
        float* orow = out + ((size_t)b*SEQ + q0 + row)*SEQ;
        #pragma unroll
        for (int i = 0; i < 16; ++i)
            orow[lane + 32*i] = vbuf[i] * inv;
    }
}

// ---------------------------------------------------------------------------
// Launch
// ---------------------------------------------------------------------------
extern "C" void kernel_launch(void* const* d_in, const int* in_sizes, int n_in,
                              void* d_out, int out_size)
{
    const float* nodes = (const float*)d_in[0];
    const float* graph = (const float*)d_in[1];
    const float* q1    = (const float*)d_in[2];
    const float* fg    = (const float*)d_in[3];
    const float* ln    = (const float*)d_in[4];
    const float* lg    = (const float*)d_in[5];
    const float* mask  = (const float*)d_in[6];
    const float* Wqf   = (const float*)d_in[7];
    const float* Wql   = (const float*)d_in[8];
    const float* Wk    = (const float*)d_in[9];
    const float* Wv    = (const float*)d_in[10];
    const float* Wqfe  = (const float*)d_in[11];
    const float* Wqle  = (const float*)d_in[12];
    const float* Wke   = (const float*)d_in[13];
    const float* Wve   = (const float*)d_in[14];
    const float* Wc1   = (const float*)d_in[15];
    const float* bc1   = (const float*)d_in[16];
    const float* Wc2   = (const float*)d_in[17];
    const float* bc2   = (const float*)d_in[18];
    float* out = (float*)d_out;

    (void)in_sizes; (void)n_in; (void)out_size;

    cudaFuncSetAttribute(proj_gemm,    cudaFuncAttributeMaxDynamicSharedMemorySize, GEMM_SMEM);
    cudaFuncSetAttribute(mh_gemm,      cudaFuncAttributeMaxDynamicSharedMemorySize, GEMM_SMEM);
    cudaFuncSetAttribute(attn_kernel,  cudaFuncAttributeMaxDynamicSharedMemorySize, ATTN_SMEM);
    cudaFuncSetAttribute(final_kernel, cudaFuncAttributeMaxDynamicSharedMemorySize, FINAL_SMEM);

    const int gemm_blocks = (NB*SEQ) / 64;   // 256

    // All 5 projection GEMMs in one launch (1280 blocks)
    proj_gemm<<<dim3(gemm_blocks, 5), 256, GEMM_SMEM>>>(
        q1, ln, fg, lg, Wqf, Wql, Wqfe, Wqle,
        nodes, graph, Wk, Wv, Wke, Wve);

    attn_kernel<<<dim3(8, 32, 2), 256, ATTN_SMEM>>>(mask);

    mh_gemm<<<gemm_blocks, 256, GEMM_SMEM>>>(Wc1, Wc2, bc1, bc2);

    final_kernel<<<dim3(16, 32), 256, FINAL_SMEM>>>(nodes, graph, mask, out);
}

// round 5
// speedup vs baseline: 1.4397x; 1.2681x over previous
#include <cuda_runtime.h>
#include <math.h>
#include <stdint.h>

// Problem constants (fixed shapes)
#define NB   32
#define SEQ  512
#define EMB  128
#define BSE  (NB*SEQ*EMB)

typedef unsigned long long ull;

// ---------------------------------------------------------------------------
// Packed fp32x2 helpers (Blackwell FFMA2 — only reachable via PTX)
// ---------------------------------------------------------------------------
__device__ __forceinline__ ull ffma2(ull a, ull b, ull c) {
    ull d;
    asm("fma.rn.f32x2 %0, %1, %2, %3;" : "=l"(d) : "l"(a), "l"(b), "l"(c));
    return d;
}
__device__ __forceinline__ ull mul2(ull a, ull b) {
    ull d;
    asm("mul.rn.f32x2 %0, %1, %2;" : "=l"(d) : "l"(a), "l"(b));
    return d;
}
__device__ __forceinline__ ull add2(ull a, ull b) {
    ull d;
    asm("add.rn.f32x2 %0, %1, %2;" : "=l"(d) : "l"(a), "l"(b));
    return d;
}
__device__ __forceinline__ ull pack2(float lo, float hi) {
    ull d;
    asm("mov.b64 %0, {%1, %2};" : "=l"(d) : "f"(lo), "f"(hi));
    return d;
}
__device__ __forceinline__ float2 unpack2(ull v) {
    float lo, hi;
    asm("mov.b64 {%0, %1}, %2;" : "=f"(lo), "=f"(hi) : "l"(v));
    return make_float2(lo, hi);
}

// ---------------------------------------------------------------------------
// Scratch (static device arrays; no allocations allowed)
// ---------------------------------------------------------------------------
__device__ float g_Q [BSE];
__device__ float g_K [BSE];
__device__ float g_V [BSE];
__device__ float g_Ke[BSE];
__device__ float g_Ve[BSE];
__device__ float g_O1[BSE];
__device__ float g_O2[BSE];
__device__ float g_MH[BSE];

// dynamic smem sizes
constexpr int GEMM_SMEM  = 64*132*4 + 128*32*16;              // 99328 B
constexpr int ATTN_SMEM  = (64*128 + 64*128 + 64*64) * 4;     // 81920 B
constexpr int FG_SMEM    = (64*132 + 128*132) * 4;            // 101376 B

// ---------------------------------------------------------------------------
// GEMM body: Y[16384,128] = sum_p Xp[16384,128] @ Wp[128,128] (+bias0+bias1)
// Block: 64 rows x 128 cols, 256 threads, each thread 2 rows x 16 cols.
// ---------------------------------------------------------------------------
__device__ __forceinline__ void gemm_body(
    const float* const* Xs, const float* const* Ws, int npair,
    const float* bias0, const float* bias1, float* Y)
{
    extern __shared__ float sm[];
    float*  sX = sm;                         // [64][132]
    float4* sW = (float4*)(sm + 64*132);     // [128][32] float4

    const int tid  = threadIdx.x;
    const int row0 = blockIdx.x * 64;
    const int r    = tid >> 3;   // 0..31
    const int cg   = tid & 7;    // cols 4*(cg+8j)+0..3

    ull acc2[2][8];
    #pragma unroll
    for (int a = 0; a < 2; ++a)
        #pragma unroll
        for (int j = 0; j < 8; ++j) acc2[a][j] = 0ull;

    for (int p = 0; p < npair; ++p) {
        const float4* Wsrc = (const float4*)Ws[p];
        #pragma unroll
        for (int i = 0; i < 16; ++i) sW[tid + i*256] = Wsrc[tid + i*256];
        const float4* Xsrc = (const float4*)(Xs[p] + (size_t)row0 * EMB);
        #pragma unroll
        for (int i = 0; i < 8; ++i) {
            int idx = tid + i*256;                       // 0..2047
            float4 v = Xsrc[idx];
            ((float4*)(sX + (idx >> 5) * 132))[idx & 31] = v;
        }
        __syncthreads();

        #pragma unroll 8
        for (int k = 0; k < 128; ++k) {
            float xa = sX[r*132 + k];
            float xb = sX[(r+32)*132 + k];
            ull xa2 = pack2(xa, xa);
            ull xb2 = pack2(xb, xb);
            const ulonglong2* w2 = (const ulonglong2*)(sW + k*32);
            #pragma unroll
            for (int j = 0; j < 4; ++j) {
                ulonglong2 w = w2[cg + 8*j];
                acc2[0][2*j  ] = ffma2(xa2, w.x, acc2[0][2*j  ]);
                acc2[0][2*j+1] = ffma2(xa2, w.y, acc2[0][2*j+1]);
                acc2[1][2*j  ] = ffma2(xb2, w.x, acc2[1][2*j  ]);
                acc2[1][2*j+1] = ffma2(xb2, w.y, acc2[1][2*j+1]);
            }
        }
        __syncthreads();
    }

    float4 bv[4];
    #pragma unroll
    for (int j = 0; j < 4; ++j) bv[j] = make_float4(0.f, 0.f, 0.f, 0.f);
    if (bias0 != nullptr) {
        #pragma unroll
        for (int j = 0; j < 4; ++j) {
            float4 a = ((const float4*)bias0)[cg + 8*j];
            float4 b = ((const float4*)bias1)[cg + 8*j];
            bv[j] = make_float4(a.x + b.x, a.y + b.y, a.z + b.z, a.w + b.w);
        }
    }

    #pragma unroll
    for (int a = 0; a < 2; ++a) {
        size_t row = (size_t)row0 + r + 32*a;
        float4* yr = (float4*)(Y + row * EMB);
        #pragma unroll
        for (int j = 0; j < 4; ++j) {
            float2 lo = unpack2(acc2[a][2*j]);
            float2 hi = unpack2(acc2[a][2*j+1]);
            float4 o = make_float4(lo.x + bv[j].x, lo.y + bv[j].y,
                                   hi.x + bv[j].z, hi.y + bv[j].w);
            yr[cg + 8*j] = o;
        }
    }
}

// Merged projection GEMMs: grid (256, 5).
__global__ __launch_bounds__(256)
void proj_gemm(const float* __restrict__ q1,  const float* __restrict__ ln,
               const float* __restrict__ fg,  const float* __restrict__ lg,
               const float* __restrict__ Wqf, const float* __restrict__ Wql,
               const float* __restrict__ Wqfe,const float* __restrict__ Wqle,
               const float* __restrict__ nodes, const float* __restrict__ graph,
               const float* __restrict__ Wk,  const float* __restrict__ Wv,
               const float* __restrict__ Wke, const float* __restrict__ Wve)
{
    const float* Xs[4];
    const float* Ws[4];
    float* Y;
    int npair;
    switch (blockIdx.y) {
        case 0: npair = 4; Xs[0]=q1; Xs[1]=ln; Xs[2]=fg; Xs[3]=lg;
                Ws[0]=Wqf; Ws[1]=Wql; Ws[2]=Wqfe; Ws[3]=Wqle; Y=g_Q; break;
        case 1: npair = 1; Xs[0]=nodes; Ws[0]=Wk;  Y=g_K;  break;
        case 2: npair = 1; Xs[0]=nodes; Ws[0]=Wv;  Y=g_V;  break;
        case 3: npair = 1; Xs[0]=graph; Ws[0]=Wke; Y=g_Ke; break;
        default:npair = 1; Xs[0]=graph; Ws[0]=Wve; Y=g_Ve; break;
    }
    gemm_body(Xs, Ws, npair, nullptr, nullptr, Y);
}

// MH = O1@Wc1 + O2@Wc2 + (bc1 + bc2)
__global__ __launch_bounds__(256)
void mh_gemm(const float* __restrict__ Wc1, const float* __restrict__ Wc2,
             const float* __restrict__ bc1, const float* __restrict__ bc2)
{
    const float* Xs[2] = { g_O1, g_O2 };
    const float* Ws[2] = { Wc1, Wc2 };
    gemm_body(Xs, Ws, 2, bc1, bc2, g_MH);
}

// ---------------------------------------------------------------------------
// Dual-MHA, MAX-FREE softmax (softmax shift-invariance; scores bounded by data,
// clamped at 60 for fp32 safety). grid = (8 qtiles, 32 batches, 2 mhas).
// h = tid>>5 (warp per head), lane owns queries {lane, lane+32}.
// ---------------------------------------------------------------------------
__global__ __launch_bounds__(256, 2)
void attn_kernel(const float* __restrict__ mask)
{
    extern __shared__ float sm[];
    float* sK  = sm;                 // [64][128]
    float* sV  = sm + 64*128;        // [64][128]
    float* sMT = sV + 64*128;        // [64 keys][64 queries]

    const int tid = threadIdx.x;
    const int b   = blockIdx.y;
    const int q0  = blockIdx.x * 64;
    const int mha = blockIdx.z;

    const float* Kg = mha ? g_Ke : g_K;
    const float* Vg = mha ? g_Ve : g_V;
    float*       Og = mha ? g_O2 : g_O1;

    const int h    = tid >> 5;   // 0..7 head
    const int lane = tid & 31;   // query a = lane, query b = lane+32

    ull qa2[8], qb2[8];
    {
        const float4* pa = (const float4*)(g_Q + ((size_t)b*SEQ + q0 + lane)*EMB + h*16);
        const float4* pb = (const float4*)(g_Q + ((size_t)b*SEQ + q0 + lane + 32)*EMB + h*16);
        #pragma unroll
        for (int i = 0; i < 4; ++i) {
            float4 va = pa[i], vb = pb[i];
            qa2[2*i  ] = pack2(va.x*0.25f, va.y*0.25f);
            qa2[2*i+1] = pack2(va.z*0.25f, va.w*0.25f);
            qb2[2*i  ] = pack2(vb.x*0.25f, vb.y*0.25f);
            qb2[2*i+1] = pack2(vb.z*0.25f, vb.w*0.25f);
        }
    }

    float la = 0.f, lb = 0.f;
    ull aa2[8], ab2[8];
    #pragma unroll
    for (int i = 0; i < 8; ++i) { aa2[i] = 0ull; ab2[i] = 0ull; }

    const float* Kb = Kg + (size_t)b*SEQ*EMB;
    const float* Vb = Vg + (size_t)b*SEQ*EMB;
    const float* Mb = mask + ((size_t)b*SEQ + q0)*SEQ;

    for (int kt = 0; kt < 8; ++kt) {
        const int k0 = kt * 64;
        {
            const float4* src = (const float4*)(Kb + (size_t)k0*EMB);
            float4* dst = (float4*)sK;
            #pragma unroll
            for (int i = 0; i < 8; ++i) dst[tid + i*256] = src[tid + i*256];
            src = (const float4*)(Vb + (size_t)k0*EMB);
            dst = (float4*)sV;
            #pragma unroll
            for (int i = 0; i < 8; ++i) dst[tid + i*256] = src[tid + i*256];
            // mask transpose: sMT[key][query]
            const int mq = tid >> 2;
            const int mg = tid & 3;
            const float4* msrc = (const float4*)(Mb + (size_t)mq*SEQ + k0 + mg*16);
            #pragma unroll
            for (int i = 0; i < 4; ++i) {
                float4 v = msrc[i];
                int j = mg*16 + i*4;
                sMT[(j+0)*64 + mq] = v.x;
                sMT[(j+1)*64 + mq] = v.y;
                sMT[(j+2)*64 + mq] = v.z;
                sMT[(j+3)*64 + mq] = v.w;
            }
        }
        __syncthreads();

        for (int j = 0; j < 64; ++j) {
            const ulonglong2* kr = (const ulonglong2*)(sK + j*EMB + h*16);
            ulonglong2 k01 = kr[0], k23 = kr[1], k45 = kr[2], k67 = kr[3];

            // query a: two 4-deep chains
            ull sAx = mul2(qa2[0], k01.x);
            ull sAy = mul2(qa2[1], k01.y);
            sAx = ffma2(qa2[2], k23.x, sAx);
            sAy = ffma2(qa2[3], k23.y, sAy);
            sAx = ffma2(qa2[4], k45.x, sAx);
            sAy = ffma2(qa2[5], k45.y, sAy);
            sAx = ffma2(qa2[6], k67.x, sAx);
            sAy = ffma2(qa2[7], k67.y, sAy);
            float2 fa = unpack2(add2(sAx, sAy));

            ull sBx = mul2(qb2[0], k01.x);
            ull sBy = mul2(qb2[1], k01.y);
            sBx = ffma2(qb2[2], k23.x, sBx);
            sBy = ffma2(qb2[3], k23.y, sBy);
            sBx = ffma2(qb2[4], k45.x, sBx);
            sBy = ffma2(qb2[5], k45.y, sBy);
            sBx = ffma2(qb2[6], k67.x, sBx);
            sBy = ffma2(qb2[7], k67.y, sBy);
            float2 fb = unpack2(add2(sBx, sBy));

            float sa = fa.x + fa.y + sMT[j*64 + lane];
            float sb = fb.x + fb.y + sMT[j*64 + lane + 32];

            float ea = __expf(fminf(sa, 60.f));
            float eb = __expf(fminf(sb, 60.f));
            la += ea;
            lb += eb;

            const ulonglong2* vr = (const ulonglong2*)(sV + j*EMB + h*16);
            ulonglong2 v01 = vr[0], v23 = vr[1], v45 = vr[2], v67 = vr[3];
            ull ea2 = pack2(ea, ea);
            ull eb2 = pack2(eb, eb);
            aa2[0] = ffma2(ea2, v01.x, aa2[0]); aa2[1] = ffma2(ea2, v01.y, aa2[1]);
            aa2[2] = ffma2(ea2, v23.x, aa2[2]); aa2[3] = ffma2(ea2, v23.y, aa2[3]);
            aa2[4] = ffma2(ea2, v45.x, aa2[4]); aa2[5] = ffma2(ea2, v45.y, aa2[5]);
            aa2[6] = ffma2(ea2, v67.x, aa2[6]); aa2[7] = ffma2(ea2, v67.y, aa2[7]);
            ab2[0] = ffma2(eb2, v01.x, ab2[0]); ab2[1] = ffma2(eb2, v01.y, ab2[1]);
            ab2[2] = ffma2(eb2, v23.x, ab2[2]); ab2[3] = ffma2(eb2, v23.y, ab2[3]);
            ab2[4] = ffma2(eb2, v45.x, ab2[4]); ab2[5] = ffma2(eb2, v45.y, ab2[5]);
            ab2[6] = ffma2(eb2, v67.x, ab2[6]); ab2[7] = ffma2(eb2, v67.y, ab2[7]);
        }
        __syncthreads();
    }

    {
        float inv = 1.0f / la;
        float4* od = (float4*)(Og + ((size_t)b*SEQ + q0 + lane)*EMB + h*16);
        #pragma unroll
        for (int i = 0; i < 4; ++i) {
            float2 lo = unpack2(aa2[2*i]);
            float2 hi = unpack2(aa2[2*i+1]);
            od[i] = make_float4(lo.x*inv, lo.y*inv, hi.x*inv, hi.y*inv);
        }
    }
    {
        float inv = 1.0f / lb;
        float4* od = (float4*)(Og + ((size_t)b*SEQ + q0 + lane + 32)*EMB + h*16);
        #pragma unroll
        for (int i = 0; i < 4; ++i) {
            float2 lo = unpack2(ab2[2*i]);
            float2 hi = unpack2(ab2[2*i+1]);
            od[i] = make_float4(lo.x*inv, lo.y*inv, hi.x*inv, hi.y*inv);
        }
    }
}

// ---------------------------------------------------------------------------
// Final GEMM: out[b][q][n] = 10*tanh( (MH[q,:]·(nodes+graph)[n,:]) / sqrt(128) )
// grid = (4 ntiles of 128, 8 qtiles of 64, 32 b), 256 threads.
// Thread tile: 8 q (as 4 f32x2 pairs) x 4 n = 16 FFMA2 per k.
// shk stored k-major with xor-(k&28) swizzle -> conflict-free inner reads,
// 4-way (not 16-way) one-time transpose stores.
// ---------------------------------------------------------------------------
__global__ __launch_bounds__(256, 2)
void final_gemm(const float* __restrict__ nodes, const float* __restrict__ graph,
                float* __restrict__ out)
{
    extern __shared__ float sm[];
    float* sMH = sm;              // [64 q][132 k]  (row-major, broadcast reads)
    float* sSK = sm + 64*132;     // [128 k][132 n] (transposed + swizzled)

    const int tid = threadIdx.x;
    const int b   = blockIdx.z;
    const int q0  = blockIdx.y * 64;
    const int n0  = blockIdx.x * 128;

    // MH tile: 64 q x 128 k, row-major (float4 stores, conflict-free)
    {
        const float4* msrc = (const float4*)(g_MH + ((size_t)b*SEQ + q0)*EMB);
        #pragma unroll
        for (int i = 0; i < 8; ++i) {
            int idx = tid + i*256;                      // 0..2047
            float4 v = msrc[idx];
            ((float4*)(sMH + (idx >> 5)*132))[idx & 31] = v;
        }
    }
    // shk tile: 128 n x 128 k -> transposed into sSK[k][n^ (k&28)]
    {
        #pragma unroll
        for (int i = 0; i < 16; ++i) {
            int idx = tid + i*256;                      // 0..4095
            int nr  = idx >> 5;                         // 0..127
            int kq  = idx & 31;
            const float4* ns = (const float4*)(nodes + ((size_t)b*SEQ + n0 + nr)*EMB) + kq;
            const float4* gs = (const float4*)(graph + ((size_t)b*SEQ + n0 + nr)*EMB) + kq;
            float4 a = *ns, c = *gs;
            a.x += c.x; a.y += c.y; a.z += c.z; a.w += c.w;
            int k = kq * 4;
            sSK[(k+0)*132 + (nr ^ ((k+0)&28))] = a.x;
            sSK[(k+1)*132 + (nr ^ ((k+1)&28))] = a.y;
            sSK[(k+2)*132 + (nr ^ ((k+2)&28))] = a.z;
            sSK[(k+3)*132 + (nr ^ ((k+3)&28))] = a.w;
        }
    }
    __syncthreads();

    const int qg = tid >> 5;    // 0..7  -> q rows qg*8..+7
    const int ng = tid & 31;    // 0..31 -> n cols ng*4..+3
    const float* mb = sMH + qg*8*132;

    ull acc[4][4];
    #pragma unroll
    for (int qp = 0; qp < 4; ++qp)
        #pragma unroll
        for (int n = 0; n < 4; ++n) acc[qp][n] = 0ull;

    #pragma unroll 4
    for (int k = 0; k < 128; ++k) {
        float4 nv = *(const float4*)(sSK + k*132 + ((ng*4) ^ (k & 28)));
        ull n2x = pack2(nv.x, nv.x);
        ull n2y = pack2(nv.y, nv.y);
        ull n2z = pack2(nv.z, nv.z);
        ull n2w = pack2(nv.w, nv.w);
        #pragma unroll
        for (int qp = 0; qp < 4; ++qp) {
            ull q2 = pack2(mb[(2*qp)*132 + k], mb[(2*qp+1)*132 + k]);
            acc[qp][0] = ffma2(q2, n2x, acc[qp][0]);
            acc[qp][1] = ffma2(q2, n2y, acc[qp][1]);
            acc[qp][2] = ffma2(q2, n2z, acc[qp][2]);
            acc[qp][3] = ffma2(q2, n2w, acc[qp][3]);
        }
    }

    // epilogue: 10*tanh(x/sqrt(128)) = 10 - 20/(exp(2x/sqrt(128))+1)
    #pragma unroll
    for (int r = 0; r < 8; ++r) {
        const int qp = r >> 1;
        float v[4];
        #pragma unroll
        for (int n = 0; n < 4; ++n) {
            float2 f = unpack2(acc[qp][n]);
            v[n] = (r & 1) ? f.y : f.x;
        }
        float4 o;
        {
            float e0 = __expf(v[0] * 0.17677669529663689f);
            float e1 = __expf(v[1] * 0.17677669529663689f);
            float e2 = __expf(v[2] * 0.17677669529663689f);
            float e3 = __expf(v[3] * 0.17677669529663689f);
            o.x = 10.0f - __fdividef(20.0f, e0 + 1.0f);
            o.y = 10.0f - __fdividef(20.0f, e1 + 1.0f);
            o.z = 10.0f - __fdividef(20.0f, e2 + 1.0f);
            o.w = 10.0f - __fdividef(20.0f, e3 + 1.0f);
        }
        *(float4*)(out + ((size_t)b*SEQ + q0 + qg*8 + r)*SEQ + n0 + ng*4) = o;
    }
}

// ---------------------------------------------------------------------------
// In-place masked softmax over out rows (max-free: logits bounded by +-10 +
// mask<=0; clamp at 80 for fp32 safety). One warp per row, 8 rows/block.
// ---------------------------------------------------------------------------
__global__ __launch_bounds__(256)
void softmax_kernel(const float* __restrict__ mask, float* __restrict__ out)
{
    const int row  = blockIdx.x * 8 + (threadIdx.x >> 5);
    const int lane = threadIdx.x & 31;
    float4* po = (float4*)(out + (size_t)row * SEQ);
    const float4* pm = (const float4*)(mask + (size_t)row * SEQ);

    float4 e[4];
    float s = 0.f;
    #pragma unroll
    for (int i = 0; i < 4; ++i) {
        float4 v = po[lane + 32*i];
        float4 m = pm[lane + 32*i];
        e[i].x = __expf(fminf(v.x + m.x, 80.f));
        e[i].y = __expf(fminf(v.y + m.y, 80.f));
        e[i].z = __expf(fminf(v.z + m.z, 80.f));
        e[i].w = __expf(fminf(v.w + m.w, 80.f));
        s += e[i].x + e[i].y + e[i].z + e[i].w;
    }
    #pragma unroll
    for (int off = 16; off > 0; off >>= 1)
        s += __shfl_xor_sync(0xffffffffu, s, off);
    float inv = 1.0f / s;
    #pragma unroll
    for (int i = 0; i < 4; ++i) {
        float4 o = e[i];
        o.x *= inv; o.y *= inv; o.z *= inv; o.w *= inv;
        po[lane + 32*i] = o;
    }
}

// ---------------------------------------------------------------------------
// Launch
// ---------------------------------------------------------------------------
extern "C" void kernel_launch(void* const* d_in, const int* in_sizes, int n_in,
                              void* d_out, int out_size)
{
    const float* nodes = (const float*)d_in[0];
    const float* graph = (const float*)d_in[1];
    const float* q1    = (const float*)d_in[2];
    const float* fg    = (const float*)d_in[3];
    const float* ln    = (const float*)d_in[4];
    const float* lg    = (const float*)d_in[5];
    const float* mask  = (const float*)d_in[6];
    const float* Wqf   = (const float*)d_in[7];
    const float* Wql   = (const float*)d_in[8];
    const float* Wk    = (const float*)d_in[9];
    const float* Wv    = (const float*)d_in[10];
    const float* Wqfe  = (const float*)d_in[11];
    const float* Wqle  = (const float*)d_in[12];
    const float* Wke   = (const float*)d_in[13];
    const float* Wve   = (const float*)d_in[14];
    const float* Wc1   = (const float*)d_in[15];
    const float* bc1   = (const float*)d_in[16];
    const float* Wc2   = (const float*)d_in[17];
    const float* bc2   = (const float*)d_in[18];
    float* out = (float*)d_out;

    (void)in_sizes; (void)n_in; (void)out_size;

    cudaFuncSetAttribute(proj_gemm,   cudaFuncAttributeMaxDynamicSharedMemorySize, GEMM_SMEM);
    cudaFuncSetAttribute(mh_gemm,     cudaFuncAttributeMaxDynamicSharedMemorySize, GEMM_SMEM);
    cudaFuncSetAttribute(attn_kernel, cudaFuncAttributeMaxDynamicSharedMemorySize, ATTN_SMEM);
    cudaFuncSetAttribute(final_gemm,  cudaFuncAttributeMaxDynamicSharedMemorySize, FG_SMEM);

    const int gemm_blocks = (NB*SEQ) / 64;   // 256

    proj_gemm<<<dim3(gemm_blocks, 5), 256, GEMM_SMEM>>>(
        q1, ln, fg, lg, Wqf, Wql, Wqfe, Wqle,
        nodes, graph, Wk, Wv, Wke, Wve);

    attn_kernel<<<dim3(8, 32, 2), 256, ATTN_SMEM>>>(mask);

    mh_gemm<<<gemm_blocks, 256, GEMM_SMEM>>>(Wc1, Wc2, bc1, bc2);

    final_gemm<<<dim3(4, 8, 32), 256, FG_SMEM>>>(nodes, graph, out);

    softmax_kernel<<<(NB*SEQ)/8, 256>>>(mask, out);
}